// round 9
// baseline (speedup 1.0000x reference)
#include <cuda_runtime.h>
#include <cuda_bf16.h>
#include <cstdint>

// ======================= constants =======================
#define NH      16
#define NQ      4096
#define NKV     8192
#define HD      128
#define PREFIX  (NKV - NQ)
#define BQ      128
#define BK      64
#define THREADS 256
#define LOG2E   1.4426950408889634f
#define SOFT_C  10.0f

#define KVELEMS (NH * NKV * HD)        // 16,777,216 per tensor

// bf16 tiles: 64 rows x 128 elems, row stride 272B (+16B pad, ldsm conflict-free)
#define KROW    272
#define KTILE   17408                  // 64*272
// smem layout (bytes), all double buffered
#define KB(b)   ((b) * 34816)          // K hi+lo          [0, 69632)
#define VB(b)   (69632 + (b) * 34816)  // V hi+lo          [69632, 139264)
#define MSB(b)  (139264 + (b) * 32768) // mask f32         [139264, 204800)
#define SMEM_BYTES 204800
// Q staging scratch (prologue only; disjoint from tile-0 targets KB(0)/VB(0)/MSB(0))
#define QSH     VB(1)
#define QSL     KB(1)

// ======================= persistent bf16 hi/lo copies of K and V =======================
__device__ __align__(16) __nv_bfloat16 g_kh[KVELEMS];
__device__ __align__(16) __nv_bfloat16 g_kl[KVELEMS];
__device__ __align__(16) __nv_bfloat16 g_vh[KVELEMS];
__device__ __align__(16) __nv_bfloat16 g_vl[KVELEMS];

// ======================= PTX helpers (base ISA only) =======================
__device__ __forceinline__ uint32_t smem_to_u32(const void* p) {
    uint32_t a;
    asm("{ .reg .u64 t; cvta.to.shared.u64 t, %1; cvt.u32.u64 %0, t; }" : "=r"(a) : "l"(p));
    return a;
}
__device__ __forceinline__ void ldsm_x4(uint32_t addr, uint32_t* r) {
    asm volatile("ldmatrix.sync.aligned.m8n8.x4.shared.b16 {%0,%1,%2,%3}, [%4];"
                 : "=r"(r[0]), "=r"(r[1]), "=r"(r[2]), "=r"(r[3]) : "r"(addr));
}
__device__ __forceinline__ void ldsm_x4_t(uint32_t addr, uint32_t* r) {
    asm volatile("ldmatrix.sync.aligned.m8n8.x4.trans.shared.b16 {%0,%1,%2,%3}, [%4];"
                 : "=r"(r[0]), "=r"(r[1]), "=r"(r[2]), "=r"(r[3]) : "r"(addr));
}
__device__ __forceinline__ void mma_bf16(float* c, const uint32_t* a, uint32_t b0, uint32_t b1) {
    asm volatile("mma.sync.aligned.m16n8k16.row.col.f32.bf16.bf16.f32 "
                 "{%0,%1,%2,%3}, {%4,%5,%6,%7}, {%8,%9}, {%0,%1,%2,%3};"
                 : "+f"(c[0]), "+f"(c[1]), "+f"(c[2]), "+f"(c[3])
                 : "r"(a[0]), "r"(a[1]), "r"(a[2]), "r"(a[3]), "r"(b0), "r"(b1));
}
__device__ __forceinline__ uint32_t packbf(float lo, float hi) {
    uint32_t r;
    asm("cvt.rn.bf16x2.f32 %0, %1, %2;" : "=r"(r) : "f"(hi), "f"(lo));
    return r;
}
__device__ __forceinline__ float ex2f(float x) {
    float r; asm("ex2.approx.f32 %0, %1;" : "=f"(r) : "f"(x)); return r;
}
__device__ __forceinline__ void split2(float a, float b, uint32_t& hi, uint32_t& lo) {
    hi = packbf(a, b);
    float fa = __uint_as_float(hi << 16);
    float fb = __uint_as_float(hi & 0xffff0000u);
    lo = packbf(a - fa, b - fb);
}
__device__ __forceinline__ void cp_async16(uint32_t dst, const void* src) {
    asm volatile("cp.async.cg.shared.global [%0], [%1], 16;" :: "r"(dst), "l"(src) : "memory");
}
#define CP_COMMIT() asm volatile("cp.async.commit_group;" ::: "memory")
#define CP_WAIT(n)  asm volatile("cp.async.wait_group %0;" :: "n"(n) : "memory")

// ======================= prep kernel: K/V f32 -> bf16 hi/lo =======================
__global__ void __launch_bounds__(256)
prep_kernel(const float* __restrict__ K, const float* __restrict__ V)
{
    const size_t n4 = KVELEMS / 4;
    size_t i = (size_t)blockIdx.x * 256 + threadIdx.x;   // one float4 per thread
    const float* src;
    __nv_bfloat16 *dh, *dl;
    size_t j;
    if (i < n4) { src = K; dh = g_kh; dl = g_kl; j = i; }
    else        { src = V; dh = g_vh; dl = g_vl; j = i - n4; }
    float4 v = ((const float4*)src)[j];
    uint32_t h01, l01, h23, l23;
    split2(v.x, v.y, h01, l01);
    split2(v.z, v.w, h23, l23);
    ((uint2*)dh)[j] = make_uint2(h01, h23);
    ((uint2*)dl)[j] = make_uint2(l01, l23);
}

// prefetch one 64x128 bf16 tile (256B rows) into padded smem (272B rows)
__device__ __forceinline__ void fetch_bf16_tile(uint32_t smdst, const __nv_bfloat16* gsrc, int tid) {
#pragma unroll
    for (int i = 0; i < 4; i++) {
        int gi  = tid + i * THREADS;       // 0..1023
        int row = gi >> 4, c = gi & 15;    // 16B chunks per 256B row
        cp_async16(smdst + row * KROW + c * 16, gsrc + (size_t)row * HD + c * 8);
    }
}

// fragment fetch for QK step i (i = ntg*4 + kcp)
__device__ __forceinline__ void qk_frags(uint32_t smb, int kbh, int kbl, int lane, int i,
                                         uint32_t* h0, uint32_t* l0, uint32_t* h1, uint32_t* l1) {
    const int ntg = i >> 2, kcp = i & 3;
    const uint32_t rb0 = (uint32_t)(ntg * 16 + (lane & 7)) * KROW + ((lane >> 3) << 4) + kcp * 64;
    const uint32_t rb1 = rb0 + 8 * KROW;
    ldsm_x4(smb + kbh + rb0, h0);
    ldsm_x4(smb + kbl + rb0, l0);
    ldsm_x4(smb + kbh + rb1, h1);
    ldsm_x4(smb + kbl + rb1, l1);
}

// fragment fetch for PV step i (i = kc*4 + pg)
__device__ __forceinline__ void pv_frags(uint32_t smb, int vbh, int vbl, int lane, int i,
                                         uint32_t* h0, uint32_t* l0, uint32_t* h1, uint32_t* l1) {
    const int kc = i >> 2, pg = i & 3;
    const uint32_t rv = (uint32_t)(kc * 16 + ((lane >> 3) & 1) * 8 + (lane & 7)) * KROW
                      + ((lane >> 4) << 4);
    ldsm_x4_t(smb + vbh + rv + (2 * pg) * 32,     h0);
    ldsm_x4_t(smb + vbl + rv + (2 * pg) * 32,     l0);
    ldsm_x4_t(smb + vbh + rv + (2 * pg + 1) * 32, h1);
    ldsm_x4_t(smb + vbl + rv + (2 * pg + 1) * 32, l1);
}

// ======================= main kernel =======================
__global__ void __launch_bounds__(THREADS, 1)
fsdpa_mma(const float* __restrict__ Qg, const float* __restrict__ Mg,
          float* __restrict__ Og)
{
    extern __shared__ char smem[];
    const uint32_t smb = smem_to_u32(smem);
    const int tid  = threadIdx.x;
    const int lane = tid & 31;
    const int wid  = tid >> 5;
    const int g    = lane >> 2;
    const int t2   = lane & 3;
    const int h    = blockIdx.y;
    const int q0   = (int)(gridDim.x - 1 - blockIdx.x) * BQ;  // longest work first
    const int wq   = wid * 16;

    const size_t kvbase = (size_t)h * NKV * HD;
    const int ntiles = (PREFIX + q0 + BQ) / BK;

    // ---- prefetch tile 0 (K,V bf16 hi/lo + mask) into buffer 0 ----
    fetch_bf16_tile(smb + KB(0),         g_kh + kvbase, tid);
    fetch_bf16_tile(smb + KB(0) + KTILE, g_kl + kvbase, tid);
    fetch_bf16_tile(smb + VB(0),         g_vh + kvbase, tid);
    fetch_bf16_tile(smb + VB(0) + KTILE, g_vl + kvbase, tid);
#pragma unroll
    for (int i = 0; i < 8; i++) {
        int gi = tid + i * THREADS;
        int row = gi >> 4, c4 = gi & 15;
        cp_async16(smb + MSB(0) + row * 256 + c4 * 16, Mg + (size_t)(q0 + row) * NKV + c4 * 4);
    }
    CP_COMMIT();

    // ---- stage Q (scale folded) into scratch (buffer-1 regions), ldmatrix to regs ----
    {
        const float scale = 0.08838834764831845f;   // 1/sqrt(128)
        const float* qb = Qg + ((size_t)h * NQ + q0) * HD;
#pragma unroll
        for (int i = 0; i < 16; i++) {
            int gi  = tid + i * THREADS;
            int row = gi >> 5, c4 = (gi & 31) << 2;
            float4 v = *(const float4*)(qb + (size_t)row * HD + c4);
            v.x *= scale; v.y *= scale; v.z *= scale; v.w *= scale;
            uint32_t h01, l01, h23, l23;
            split2(v.x, v.y, h01, l01);
            split2(v.z, v.w, h23, l23);
            int off = row * KROW + c4 * 2;
            *(uint2*)(smem + QSH + off) = make_uint2(h01, h23);
            *(uint2*)(smem + QSL + off) = make_uint2(l01, l23);
        }
    }
    __syncthreads();

    uint32_t qh[8][4], ql[8][4];
    {
        const int mi = lane >> 3;
        const uint32_t ro = (uint32_t)(wq + (lane & 7) + ((mi & 1) << 3)) * KROW + ((mi >> 1) << 4);
#pragma unroll
        for (int kc = 0; kc < 8; kc++) {
            ldsm_x4(smb + QSH + ro + kc * 32, qh[kc]);
            ldsm_x4(smb + QSL + ro + kc * 32, ql[kc]);
        }
    }
    // buffer-1 regions freed after loop-top __syncthreads (t=0)

    float o[16][4];
#pragma unroll
    for (int i = 0; i < 16; i++)
#pragma unroll
        for (int j = 0; j < 4; j++) o[i][j] = 0.0f;
    float ls0 = 0.0f, ls1 = 0.0f;

    const float zb = -SOFT_C * LOG2E;

    for (int t = 0; t < ntiles; t++) {
        const int kv0 = t * BK;
        const int buf = t & 1;
        const int kbh = KB(buf), kbl = kbh + KTILE;
        const int vbh = VB(buf), vbl = vbh + KTILE;
        const float* msf = (const float*)(smem + MSB(buf));

        // tile t data arrived; all warps done with buffer buf^1 (previous tile)
        CP_WAIT(0);
        __syncthreads();

        // prefetch tile t+1 into buffer buf^1
        if (t + 1 < ntiles) {
            const size_t nb = kvbase + (size_t)(kv0 + BK) * HD;
            fetch_bf16_tile(smb + KB(buf ^ 1),         g_kh + nb, tid);
            fetch_bf16_tile(smb + KB(buf ^ 1) + KTILE, g_kl + nb, tid);
            fetch_bf16_tile(smb + VB(buf ^ 1),         g_vh + nb, tid);
            fetch_bf16_tile(smb + VB(buf ^ 1) + KTILE, g_vl + nb, tid);
#pragma unroll
            for (int i = 0; i < 8; i++) {
                int gi = tid + i * THREADS;
                int row = gi >> 4, c4 = gi & 15;
                cp_async16(smb + MSB(buf ^ 1) + row * 256 + c4 * 16,
                           Mg + (size_t)(q0 + row) * NKV + (kv0 + BK) + c4 * 4);
            }
        }
        CP_COMMIT();

        // ---- S = Q @ K^T: 16 steps, fragment loads pipelined one step ahead ----
        float s[8][4];
#pragma unroll
        for (int i = 0; i < 8; i++)
#pragma unroll
            for (int j = 0; j < 4; j++) s[i][j] = 0.0f;

        {
            uint32_t fh0[2][4], fl0[2][4], fh1[2][4], fl1[2][4];
            qk_frags(smb, kbh, kbl, lane, 0, fh0[0], fl0[0], fh1[0], fl1[0]);
#pragma unroll
            for (int i = 0; i < 16; i++) {
                const int cb = i & 1, nb2 = cb ^ 1;
                if (i < 15)
                    qk_frags(smb, kbh, kbl, lane, i + 1, fh0[nb2], fl0[nb2], fh1[nb2], fl1[nb2]);
                const int ntg = i >> 2, kc = (i & 3) * 2;
                const int nt0 = 2 * ntg, nt1 = nt0 + 1;
                mma_bf16(s[nt0], qh[kc],     fh0[cb][0], fh0[cb][1]);
                mma_bf16(s[nt1], qh[kc],     fh1[cb][0], fh1[cb][1]);
                mma_bf16(s[nt0], qh[kc],     fl0[cb][0], fl0[cb][1]);
                mma_bf16(s[nt1], qh[kc],     fl1[cb][0], fl1[cb][1]);
                mma_bf16(s[nt0], ql[kc],     fh0[cb][0], fh0[cb][1]);
                mma_bf16(s[nt1], ql[kc],     fh1[cb][0], fh1[cb][1]);
                mma_bf16(s[nt0], qh[kc + 1], fh0[cb][2], fh0[cb][3]);
                mma_bf16(s[nt1], qh[kc + 1], fh1[cb][2], fh1[cb][3]);
                mma_bf16(s[nt0], qh[kc + 1], fl0[cb][2], fl0[cb][3]);
                mma_bf16(s[nt1], qh[kc + 1], fl1[cb][2], fl1[cb][3]);
                mma_bf16(s[nt0], ql[kc + 1], fh0[cb][2], fh0[cb][3]);
                mma_bf16(s[nt1], ql[kc + 1], fh1[cb][2], fh1[cb][3]);
            }
        }

        // ---- softmax (fixed shift) ----
        {
            const int  lim0 = PREFIX + q0 + wq + g - kv0;
            const int  lim1 = lim0 + 8;
            const bool dg   = (t >= ntiles - 2);
            const float* mrow0 = msf + (wq + g) * 64;
            const float* mrow1 = mrow0 + 8 * 64;
#pragma unroll
            for (int nt = 0; nt < 8; nt++) {
                const int c = nt * 8 + t2 * 2;
                float2 m0 = *(const float2*)(mrow0 + c);
                float2 m1 = *(const float2*)(mrow1 + c);
                float z00 = fmaf(s[nt][0] + m0.x, LOG2E, zb);
                float z01 = fmaf(s[nt][1] + m0.y, LOG2E, zb);
                float z10 = fmaf(s[nt][2] + m1.x, LOG2E, zb);
                float z11 = fmaf(s[nt][3] + m1.y, LOG2E, zb);
                if (dg) {
                    if (c     > lim0) z00 = -127.0f;
                    if (c + 1 > lim0) z01 = -127.0f;
                    if (c     > lim1) z10 = -127.0f;
                    if (c + 1 > lim1) z11 = -127.0f;
                }
                float p00 = ex2f(z00), p01 = ex2f(z01);
                float p10 = ex2f(z10), p11 = ex2f(z11);
                ls0 += p00 + p01;
                ls1 += p10 + p11;
                s[nt][0] = p00; s[nt][1] = p01; s[nt][2] = p10; s[nt][3] = p11;
            }
        }

        // ---- O += P @ V: 16 steps, fragment loads pipelined one step ahead ----
        {
            uint32_t wh0[2][4], wl0[2][4], wh1[2][4], wl1[2][4];
            uint32_t ah[4], al[4];
            pv_frags(smb, vbh, vbl, lane, 0, wh0[0], wl0[0], wh1[0], wl1[0]);
#pragma unroll
            for (int i = 0; i < 16; i++) {
                const int cb = i & 1, nb2 = cb ^ 1;
                if (i < 15)
                    pv_frags(smb, vbh, vbl, lane, i + 1, wh0[nb2], wl0[nb2], wh1[nb2], wl1[nb2]);
                const int kc = i >> 2, pg = i & 3;
                if ((i & 3) == 0) {
                    split2(s[2 * kc][0],     s[2 * kc][1],     ah[0], al[0]);
                    split2(s[2 * kc][2],     s[2 * kc][3],     ah[1], al[1]);
                    split2(s[2 * kc + 1][0], s[2 * kc + 1][1], ah[2], al[2]);
                    split2(s[2 * kc + 1][2], s[2 * kc + 1][3], ah[3], al[3]);
                }
                const int p0 = 2 * pg, p1 = p0 + 1;
                mma_bf16(o[2 * p0],     ah, wh0[cb][0], wh0[cb][1]);
                mma_bf16(o[2 * p0 + 1], ah, wh0[cb][2], wh0[cb][3]);
                mma_bf16(o[2 * p1],     ah, wh1[cb][0], wh1[cb][1]);
                mma_bf16(o[2 * p1 + 1], ah, wh1[cb][2], wh1[cb][3]);
                mma_bf16(o[2 * p0],     ah, wl0[cb][0], wl0[cb][1]);
                mma_bf16(o[2 * p0 + 1], ah, wl0[cb][2], wl0[cb][3]);
                mma_bf16(o[2 * p1],     ah, wl1[cb][0], wl1[cb][1]);
                mma_bf16(o[2 * p1 + 1], ah, wl1[cb][2], wl1[cb][3]);
                mma_bf16(o[2 * p0],     al, wh0[cb][0], wh0[cb][1]);
                mma_bf16(o[2 * p0 + 1], al, wh0[cb][2], wh0[cb][3]);
                mma_bf16(o[2 * p1],     al, wh1[cb][0], wh1[cb][1]);
                mma_bf16(o[2 * p1 + 1], al, wh1[cb][2], wh1[cb][3]);
            }
        }
    }

    // ---- epilogue ----
    ls0 += __shfl_xor_sync(0xffffffffu, ls0, 1);
    ls0 += __shfl_xor_sync(0xffffffffu, ls0, 2);
    ls1 += __shfl_xor_sync(0xffffffffu, ls1, 1);
    ls1 += __shfl_xor_sync(0xffffffffu, ls1, 2);
    const float i0 = 1.0f / ls0;
    const float i1 = 1.0f / ls1;

    float* ob = Og + ((size_t)h * NQ + q0 + wq) * HD;
#pragma unroll
    for (int nt = 0; nt < 16; nt++) {
        const int c = nt * 8 + t2 * 2;
        float2 w0 = make_float2(o[nt][0] * i0, o[nt][1] * i0);
        float2 w1 = make_float2(o[nt][2] * i1, o[nt][3] * i1);
        *(float2*)(ob + (size_t)g * HD + c)       = w0;
        *(float2*)(ob + (size_t)(g + 8) * HD + c) = w1;
    }
}

extern "C" void kernel_launch(void* const* d_in, const int* in_sizes, int n_in,
                              void* d_out, int out_size)
{
    const float* q = (const float*)d_in[0];
    const float* k = (const float*)d_in[1];
    const float* v = (const float*)d_in[2];
    const float* m = (const float*)d_in[3];
    float* o = (float*)d_out;

    // 1) convert K/V to bf16 hi/lo persistent scratch
    prep_kernel<<<2 * (KVELEMS / 4) / 256, 256>>>(k, v);

    // 2) attention
    cudaFuncSetAttribute(fsdpa_mma, cudaFuncAttributeMaxDynamicSharedMemorySize, SMEM_BYTES);
    dim3 grid(NQ / BQ, NH);
    fsdpa_mma<<<grid, THREADS, SMEM_BYTES>>>(q, m, o);
}